// round 14
// baseline (speedup 1.0000x reference)
#include <cuda_runtime.h>
#include <cuda_bf16.h>
#include <cuda_fp16.h>
#include <cstdint>

// ---------------------------------------------------------------------------
// Arch feature gate: tcgen05 exists only on sm_103a / family 103f.
// ---------------------------------------------------------------------------
#if defined(__CUDA_ARCH__) && (defined(__CUDA_ARCH_FEAT_SM103_ALL) || \
    (defined(__CUDA_ARCH_FAMILY_SPECIFIC__) && (__CUDA_ARCH_FAMILY_SPECIFIC__ == 1030)))
#define TC_OK 1
#else
#define TC_OK 0
#endif

// Problem constants (fixed by dataset)
constexpr int NV = 32768;          // B*N nodes
constexpr int Hd = 128;            // hidden
constexpr int NE = 524288;         // edges
constexpr int NR = 8;              // relations
constexpr int NL = 2;              // layers
constexpr int NSLAB = NR + 1;      // 9: slab 0 = self (fp32), 1..8 = relations (fp16)

// Scratch (static device globals; no allocation at runtime)
__device__ float  g_x2[(size_t)NV * Hd];
__device__ float  g_y0[(size_t)NV * Hd];              // self-term slab, fp32
__device__ __half g_yh[(size_t)NR * NV * Hd];         // relation message slabs, fp16
__device__ float  g_wf[(size_t)NSLAB * Hd * Hd];      // fused layer-0 weights W_j @ projW
__device__ float  g_bf[NSLAB * Hd];                   // fused layer-0 biases  W_j @ projb
__device__ __align__(16) int g_hist    [NV + 4];
__device__ __align__(16) int g_rowstart[NV + 4];
__device__ __align__(16) int g_cursor  [NV + 4];
__device__ int    g_sorted [NE];                      // (type<<15) | src, grouped by dst
__device__ int    g_tc_flag;

// ---------------------------------------------------------------------------
// Static-init setup: capability probe + side stream/events (pre-capture)
// ---------------------------------------------------------------------------
__global__ void probe_kernel() { g_tc_flag = TC_OK; }

static cudaStream_t s_side;
static cudaEvent_t  s_ev_fork, s_ev_join;

static int setup_once() {
    int v = 0;
    probe_kernel<<<1, 1>>>();
    cudaMemcpyFromSymbol(&v, g_tc_flag, sizeof(int));
    cudaStreamCreateWithFlags(&s_side, cudaStreamNonBlocking);
    cudaEventCreateWithFlags(&s_ev_fork, cudaEventDisableTiming);
    cudaEventCreateWithFlags(&s_ev_join, cudaEventDisableTiming);
    return v;
}
static const int g_has_tc = setup_once();

// ---------------------------------------------------------------------------
// PTX helpers
// ---------------------------------------------------------------------------
__device__ __forceinline__ uint32_t smem_u32(const void* p) {
    uint32_t a;
    asm("{ .reg .u64 t; cvta.to.shared.u64 t, %1; cvt.u32.u64 %0, t; }" : "=r"(a) : "l"(p));
    return a;
}
__device__ __forceinline__ uint32_t elect_one() {
    uint32_t p;
    asm volatile("{\n\t.reg .pred p;\n\telect.sync _|p, 0xFFFFFFFF;\n\tselp.b32 %0, 1, 0, p;\n\t}" : "=r"(p));
    return p;
}
__device__ __forceinline__ uint32_t f2tf32(float f) {
    uint32_t u;
    asm("cvt.rna.tf32.f32 %0, %1;" : "=r"(u) : "f"(f));
    return u;
}

#if TC_OK
#define TC_ALLOC(sm, n)   asm volatile("tcgen05.alloc.cta_group::1.sync.aligned.shared::cta.b32 [%0], %1;" :: "r"(sm), "r"(n) : "memory")
#define TC_DEALLOC(t, n)  asm volatile("tcgen05.dealloc.cta_group::1.sync.aligned.b32 %0, %1;" :: "r"(t), "r"(n))
#define TC_RELINQ()       asm volatile("tcgen05.relinquish_alloc_permit.cta_group::1.sync.aligned;")
#define TC_COMMIT(mb)     asm volatile("tcgen05.commit.cta_group::1.mbarrier::arrive::one.shared::cluster.b64 [%0];" :: "r"(mb) : "memory")
#define TC_WAIT_LD()      asm volatile("tcgen05.wait::ld.sync.aligned;" ::: "memory")
#define TC_FENCE_AFTER()  asm volatile("tcgen05.fence::after_thread_sync;" ::: "memory")
#define TC_FENCE_BEFORE() asm volatile("tcgen05.fence::before_thread_sync;" ::: "memory")
#endif

#define MBAR_INIT(mb, c)  asm volatile("mbarrier.init.shared.b64 [%0], %1;" :: "r"(mb), "r"(c) : "memory")
#define MBAR_INVAL(mb)    asm volatile("mbarrier.inval.shared.b64 [%0];" :: "r"(mb) : "memory")

__device__ __forceinline__ void mbar_wait(uint32_t mb, uint32_t parity) {
    asm volatile(
        "{\n\t.reg .pred P1;\n\t"
        "WL_%=:\n\t"
        "mbarrier.try_wait.parity.acquire.cta.shared::cta.b64 P1, [%0], %1, 0x989680;\n\t"
        "@P1 bra.uni WD_%=;\n\t"
        "bra.uni WL_%=;\n\t"
        "WD_%=:\n\t}"
        :: "r"(mb), "r"(parity) : "memory");
}

#if TC_OK
__device__ __forceinline__ void mma_tf32_ss(uint32_t d, uint64_t ad, uint64_t bd,
                                            uint32_t idesc, uint32_t en) {
    asm volatile(
        "{\n\t.reg .pred p;\n\tsetp.ne.u32 p, %5, 0;\n\t"
        "tcgen05.mma.cta_group::1.kind::tf32 [%0], %1, %2, %3, {%4, %4, %4, %4}, p;\n\t}"
        :: "r"(d), "l"(ad), "l"(bd), "r"(idesc), "r"(0u), "r"(en) : "memory");
}

__device__ __forceinline__ void ldtm_x32(uint32_t* r, uint32_t addr) {
    asm volatile(
        "tcgen05.ld.sync.aligned.32x32b.x32.b32 "
        "{%0,%1,%2,%3,%4,%5,%6,%7,%8,%9,%10,%11,%12,%13,%14,%15,"
        "%16,%17,%18,%19,%20,%21,%22,%23,%24,%25,%26,%27,%28,%29,%30,%31}, [%32];"
        : "=r"(r[0]), "=r"(r[1]), "=r"(r[2]), "=r"(r[3]), "=r"(r[4]), "=r"(r[5]), "=r"(r[6]), "=r"(r[7]),
          "=r"(r[8]), "=r"(r[9]), "=r"(r[10]), "=r"(r[11]), "=r"(r[12]), "=r"(r[13]), "=r"(r[14]), "=r"(r[15]),
          "=r"(r[16]), "=r"(r[17]), "=r"(r[18]), "=r"(r[19]), "=r"(r[20]), "=r"(r[21]), "=r"(r[22]), "=r"(r[23]),
          "=r"(r[24]), "=r"(r[25]), "=r"(r[26]), "=r"(r[27]), "=r"(r[28]), "=r"(r[29]), "=r"(r[30]), "=r"(r[31])
        : "r"(addr));
}
#endif

// SW128 K-major blocked-atom layout for a 128x128 fp32 tile.
__device__ __forceinline__ uint32_t tile_off(int row, int k) {
    uint32_t off = ((uint32_t)((k >> 5) * 16 + (row >> 3)) << 10)
                 + ((uint32_t)(row & 7) << 7) + ((uint32_t)(k & 31) << 2);
    return off ^ ((off >> 3) & 0x70);
}

// smem descriptor: SW128, version=1, LBO=1, SBO=64
__device__ __forceinline__ uint64_t make_desc(uint32_t base) {
    const uint64_t BASE = (uint64_t(2) << 61) | (uint64_t(1) << 46)
                        | (uint64_t(64) << 32) | (uint64_t(1) << 16);
    return BASE | ((uint64_t)(base >> 4) & 0x3FFF);
}

constexpr uint32_t IDESC_TF32 = (1u << 4) | (2u << 7) | (2u << 10) | (16u << 17) | (8u << 24);

// Dynamic SMEM layout (tgemm9)
constexpr int SMEM_TMEM = 0;
constexpr int SMEM_MB0  = 8;
constexpr int SMEM_MB1  = 16;
constexpr int SMEM_A    = 1024;
constexpr int SMEM_W0   = SMEM_A  + 65536;
constexpr int SMEM_W1   = SMEM_W0 + 65536;
constexpr int SMEM_TOTAL9 = SMEM_W1 + 65536 + 128;
constexpr int WF_SMEM = (Hd * Hd + 16 * Hd) * 4;   // projW (64K) + 16 W rows (8K)

// ---------------------------------------------------------------------------
// Weight fusion for layer 0:  wf[j] = W_j @ projW,  bf[j] = W_j @ projb
// grid (8, 9): blockIdx.y = slab j, blockIdx.x = 16-row chunk. 256 threads.
// ---------------------------------------------------------------------------
__global__ void __launch_bounds__(256)
wfuse_kernel(const float* __restrict__ projW, const float* __restrict__ projb,
             const float* __restrict__ selfW, const float* __restrict__ relW,
             float* __restrict__ wf, float* __restrict__ bf)
{
    extern __shared__ float sdyn[];
    float* sP = sdyn;                 // [128][128] projW
    float* sW = sdyn + Hd * Hd;       // [16][128]  W_j rows

    const int j  = blockIdx.y;
    const int rb = blockIdx.x;        // row block (16 rows)
    const int t  = threadIdx.x;
    const float* Wj = (j == 0) ? selfW : (relW + (size_t)(j - 1) * Hd * Hd);

    for (int i = t; i < Hd * Hd / 4; i += 256)
        ((float4*)sP)[i] = ((const float4*)projW)[i];
    for (int i = t; i < 16 * Hd / 4; i += 256)
        ((float4*)sW)[i] = ((const float4*)(Wj + (size_t)rb * 16 * Hd))[i];
    __syncthreads();

    const int rl   = t >> 4;          // local row 0..15
    const int hseg = t & 15;          // 8-col segment
    float acc[8] = {0, 0, 0, 0, 0, 0, 0, 0};
    float bacc = 0.0f;
#pragma unroll 4
    for (int k = 0; k < Hd; k++) {
        const float wv = sW[rl * Hd + k];
        const float* pr = sP + k * Hd + hseg * 8;
#pragma unroll
        for (int hh = 0; hh < 8; hh++) acc[hh] += wv * pr[hh];
        if (hseg == 0) bacc += wv * projb[k];
    }
    const int g = rb * 16 + rl;
    float* orow = wf + ((size_t)j * Hd + g) * Hd + hseg * 8;
#pragma unroll
    for (int hh = 0; hh < 8; hh++) orow[hh] = acc[hh];
    if (hseg == 0) bf[j * Hd + g] = bacc;
}

// ---------------------------------------------------------------------------
// 9-slab GEMM: one CTA = one 128-row x-block; A loaded once; 9 weights stream
// through double-buffered smem; D ping-pongs between two TMEM buffers.
// MODE 0 (layer 0): A = cemb[cid]+kemb[kid] gathered; weights = fused wf;
//                   epilogue adds fused bias bf[j].
// MODE 1 (layer 1): A = node states; weights = selfW / relW; no bias.
// Slab 0 -> y0 (fp32); slabs 1..8 -> yh (fp16).
// ---------------------------------------------------------------------------
template <int MODE>
__global__ void __launch_bounds__(128, 1)
tgemm9(const float* __restrict__ Asrc,
       const int* __restrict__ cid, const int* __restrict__ kid,
       const float* __restrict__ cemb, const float* __restrict__ kemb,
       const float* __restrict__ wf,
       const float* __restrict__ selfW, const float* __restrict__ relW,
       const float* __restrict__ biasf,
       float* __restrict__ Y0out, __half* __restrict__ Yhout)
{
#if TC_OK
    extern __shared__ char smem[];
    const uint32_t sb = smem_u32(smem);
    const int tid = threadIdx.x;
    const int wid = tid >> 5;
    const int lid = tid & 31;
    const int vbase = blockIdx.x * 128;

    if (wid == 0) TC_ALLOC(sb + SMEM_TMEM, 256);
    else          TC_RELINQ();
    __syncthreads();
    uint32_t tmem;
    asm volatile("ld.shared.b32 %0, [%1];" : "=r"(tmem) : "r"(sb + SMEM_TMEM));

    if (tid == 0) {
        MBAR_INIT(sb + SMEM_MB0, 1);
        MBAR_INIT(sb + SMEM_MB1, 1);
    }

    // A row (row = tid)
    if (MODE == 0) {
        const float4* ar = (const float4*)(cemb + (size_t)cid[vbase + tid] * Hd);
        const float4* kr = (const float4*)(kemb + (size_t)kid[vbase + tid] * Hd);
#pragma unroll
        for (int c4 = 0; c4 < 32; c4++) {
            float4 a = ar[c4];
            const float4 k = kr[c4];
            a.x += k.x; a.y += k.y; a.z += k.z; a.w += k.w;
            *(uint4*)(smem + SMEM_A + tile_off(tid, c4 * 4)) =
                make_uint4(f2tf32(a.x), f2tf32(a.y), f2tf32(a.z), f2tf32(a.w));
        }
    } else {
        const float4* ar = (const float4*)(Asrc + (size_t)(vbase + tid) * Hd);
#pragma unroll
        for (int c4 = 0; c4 < 32; c4++) {
            const float4 a = ar[c4];
            *(uint4*)(smem + SMEM_A + tile_off(tid, c4 * 4)) =
                make_uint4(f2tf32(a.x), f2tf32(a.y), f2tf32(a.z), f2tf32(a.w));
        }
    }
    // W_0 into buffer 0
    {
        const float* W0 = (MODE == 0) ? wf : selfW;
        const float4* wr = (const float4*)(W0 + (size_t)tid * Hd);
#pragma unroll
        for (int c4 = 0; c4 < 32; c4++) {
            const float4 w = wr[c4];
            *(uint4*)(smem + SMEM_W0 + tile_off(tid, c4 * 4)) =
                make_uint4(f2tf32(w.x), f2tf32(w.y), f2tf32(w.z), f2tf32(w.w));
        }
    }
    asm volatile("fence.proxy.async.shared::cta;" ::: "memory");
    TC_FENCE_BEFORE();
    __syncthreads();

    const uint64_t ad = make_desc(sb + SMEM_A);
    const int row = wid * 32 + lid;

    for (int j = 0; j < NSLAB; j++) {
        const int buf = j & 1;
        const uint32_t dtm = tmem + buf * 128;

        if (wid == 0) {
            TC_FENCE_AFTER();
            const uint64_t bd = make_desc(sb + (buf ? SMEM_W1 : SMEM_W0));
            if (elect_one()) {
#pragma unroll
                for (int s = 0; s < 16; s++) {
                    const uint64_t off = (uint64_t)((s >> 2) * 1024 + (s & 3) * 2);
                    mma_tf32_ss(dtm, ad + off, bd + off, IDESC_TF32, s > 0 ? 1u : 0u);
                }
                TC_COMMIT(sb + (buf ? SMEM_MB1 : SMEM_MB0));
            }
        }

        if (j + 1 < NSLAB) {
            const float* Wn = (MODE == 0) ? (wf + (size_t)(j + 1) * Hd * Hd)
                                          : (relW + (size_t)j * Hd * Hd);
            const float4* wr = (const float4*)(Wn + (size_t)tid * Hd);
            char* wb = smem + ((j + 1) & 1 ? SMEM_W1 : SMEM_W0);
#pragma unroll
            for (int c4 = 0; c4 < 32; c4++) {
                const float4 w = wr[c4];
                *(uint4*)(wb + tile_off(tid, c4 * 4)) =
                    make_uint4(f2tf32(w.x), f2tf32(w.y), f2tf32(w.z), f2tf32(w.w));
            }
        }

        mbar_wait(sb + (buf ? SMEM_MB1 : SMEM_MB0), (j >> 1) & 1);
        TC_FENCE_AFTER();

        const float* bp = (MODE == 0) ? (biasf + j * Hd) : nullptr;
        if (j == 0) {
            float* crow = Y0out + (size_t)(vbase + row) * Hd;
#pragma unroll
            for (int ch = 0; ch < 4; ch++) {
                uint32_t d[32];
                ldtm_x32(d, dtm + ch * 32);
                TC_WAIT_LD();
#pragma unroll
                for (int q = 0; q < 8; q++) {
                    float4 o = make_float4(
                        __uint_as_float(d[q*4+0]), __uint_as_float(d[q*4+1]),
                        __uint_as_float(d[q*4+2]), __uint_as_float(d[q*4+3]));
                    if (MODE == 0) {
                        o.x += bp[ch*32 + q*4+0]; o.y += bp[ch*32 + q*4+1];
                        o.z += bp[ch*32 + q*4+2]; o.w += bp[ch*32 + q*4+3];
                    }
                    *(float4*)(crow + ch * 32 + q * 4) = o;
                }
            }
        } else {
            __half* crow = Yhout + ((size_t)(j - 1) * NV + (size_t)(vbase + row)) * Hd;
#pragma unroll
            for (int ch = 0; ch < 4; ch++) {
                uint32_t d[32];
                ldtm_x32(d, dtm + ch * 32);
                TC_WAIT_LD();
                uint32_t h2[16];
#pragma unroll
                for (int k2 = 0; k2 < 16; k2++) {
                    float lo = __uint_as_float(d[2*k2]);
                    float hi = __uint_as_float(d[2*k2+1]);
                    if (MODE == 0) { lo += bp[ch*32 + 2*k2]; hi += bp[ch*32 + 2*k2+1]; }
                    const __half2 hh = __floats2half2_rn(lo, hi);
                    h2[k2] = *(const uint32_t*)&hh;
                }
                uint4* dstp = (uint4*)(crow + ch * 32);
#pragma unroll
                for (int q = 0; q < 4; q++)
                    dstp[q] = make_uint4(h2[4*q+0], h2[4*q+1], h2[4*q+2], h2[4*q+3]);
            }
        }
        TC_FENCE_BEFORE();
        asm volatile("fence.proxy.async.shared::cta;" ::: "memory");
        __syncthreads();
    }

    if (tid == 0) { MBAR_INVAL(sb + SMEM_MB0); MBAR_INVAL(sb + SMEM_MB1); }
    __syncthreads();
    if (wid == 0) TC_DEALLOC(tmem, 256);
#endif
}

// ---------------------------------------------------------------------------
// Fallback SIMT fp32 GEMM — used only if tcgen05 unavailable.
// ---------------------------------------------------------------------------
__device__ float g_x_fb[(size_t)NV * Hd];   // fallback-only x buffer

template <int MODE>
__launch_bounds__(256)
__global__ void gemm_fb(const float* __restrict__ Asrc,
                        const int*   __restrict__ cid,
                        const int*   __restrict__ kid,
                        const float* __restrict__ cemb,
                        const float* __restrict__ kemb,
                        const float* __restrict__ selfW,
                        const float* __restrict__ relW,
                        const float* __restrict__ bias,
                        float* __restrict__ Cout,
                        __half* __restrict__ Hout)
{
    __shared__ float As[32][132];
    __shared__ float Ws[32][132];
    __shared__ int   s_cid[128];
    __shared__ int   s_kid[128];

    const int tid = threadIdx.x;
    const int tx = tid & 15;
    const int ty = tid >> 4;
    const int vbase = blockIdx.x * 128;

    const float* W;
    float* C = nullptr;
    __half* CH = nullptr;
    int jslab = 0;
    if (MODE == 0) {
        W = relW;
        C = Cout + (size_t)vbase * Hd;
    } else {
        jslab = blockIdx.y;
        W = (jslab == 0) ? selfW : (relW + (size_t)(jslab - 1) * Hd * Hd);
        if (jslab == 0) C = Cout + (size_t)vbase * Hd;
        else            CH = Hout + ((size_t)(jslab - 1) * NV + (size_t)vbase) * Hd;
    }

    if (MODE == 0) {
        if (tid < 128) {
            s_cid[tid] = cid[vbase + tid];
            s_kid[tid] = kid[vbase + tid];
        }
        __syncthreads();
    }

    float acc[8][8];
#pragma unroll
    for (int i = 0; i < 8; i++)
#pragma unroll
        for (int j = 0; j < 8; j++) acc[i][j] = 0.0f;

#pragma unroll
    for (int kc = 0; kc < Hd; kc += 32) {
#pragma unroll
        for (int rep = 0; rep < 4; rep++) {
            const int i   = tid + rep * 256;
            const int r   = i >> 3;
            const int c4  = i & 7;
            float4 a;
            if (MODE == 0) {
                const float4 av = ((const float4*)(cemb + (size_t)s_cid[r] * Hd + kc))[c4];
                const float4 kv = ((const float4*)(kemb + (size_t)s_kid[r] * Hd + kc))[c4];
                a = make_float4(av.x + kv.x, av.y + kv.y, av.z + kv.z, av.w + kv.w);
            } else {
                a = *(const float4*)(Asrc + (size_t)(vbase + r) * Hd + kc + c4 * 4);
            }
            As[c4 * 4 + 0][r] = a.x; As[c4 * 4 + 1][r] = a.y;
            As[c4 * 4 + 2][r] = a.z; As[c4 * 4 + 3][r] = a.w;
            const float4 w = *(const float4*)(W + (size_t)r * Hd + kc + c4 * 4);
            Ws[c4 * 4 + 0][r] = w.x; Ws[c4 * 4 + 1][r] = w.y;
            Ws[c4 * 4 + 2][r] = w.z; Ws[c4 * 4 + 3][r] = w.w;
        }
        __syncthreads();

#pragma unroll
        for (int k = 0; k < 32; k++) {
            const float4 a0 = *(const float4*)&As[k][ty * 8];
            const float4 a1 = *(const float4*)&As[k][ty * 8 + 4];
            const float4 w0 = *(const float4*)&Ws[k][tx * 8];
            const float4 w1 = *(const float4*)&Ws[k][tx * 8 + 4];
            const float a[8] = {a0.x, a0.y, a0.z, a0.w, a1.x, a1.y, a1.z, a1.w};
            const float w[8] = {w0.x, w0.y, w0.z, w0.w, w1.x, w1.y, w1.z, w1.w};
#pragma unroll
            for (int i = 0; i < 8; i++)
#pragma unroll
                for (int j = 0; j < 8; j++) acc[i][j] += a[i] * w[j];
        }
        __syncthreads();
    }

    float b0[8];
    if (MODE == 0) {
#pragma unroll
        for (int j = 0; j < 8; j++) b0[j] = bias[tx * 8 + j];
    }
#pragma unroll
    for (int i = 0; i < 8; i++) {
        const int r = ty * 8 + i;
        if (MODE == 0) {
            *(float4*)(C + (size_t)r * Hd + tx * 8) =
                make_float4(acc[i][0] + b0[0], acc[i][1] + b0[1],
                            acc[i][2] + b0[2], acc[i][3] + b0[3]);
            *(float4*)(C + (size_t)r * Hd + tx * 8 + 4) =
                make_float4(acc[i][4] + b0[4], acc[i][5] + b0[5],
                            acc[i][6] + b0[6], acc[i][7] + b0[7]);
        } else if (jslab == 0) {
            *(float4*)(C + (size_t)r * Hd + tx * 8) =
                make_float4(acc[i][0], acc[i][1], acc[i][2], acc[i][3]);
            *(float4*)(C + (size_t)r * Hd + tx * 8 + 4) =
                make_float4(acc[i][4], acc[i][5], acc[i][6], acc[i][7]);
        } else {
            uint32_t h2[4];
#pragma unroll
            for (int q = 0; q < 4; q++) {
                const __half2 hh = __floats2half2_rn(acc[i][2*q], acc[i][2*q+1]);
                h2[q] = *(const uint32_t*)&hh;
            }
            *(uint4*)(CH + (size_t)r * Hd + tx * 8) = make_uint4(h2[0], h2[1], h2[2], h2[3]);
        }
    }
}

// ---------------------------------------------------------------------------
// CSR build: histogram -> fast scan (1 CTA, vectorized + shfl) -> placement
// ---------------------------------------------------------------------------
__launch_bounds__(256)
__global__ void zero_int_kernel(int* __restrict__ p, int n)
{
    const int i = blockIdx.x * 256 + threadIdx.x;
    if (i < n) p[i] = 0;
}

__launch_bounds__(256)
__global__ void hist_kernel(const int* __restrict__ dst, int* __restrict__ hist)
{
    const int e = blockIdx.x * 256 + threadIdx.x;
    atomicAdd(&hist[dst[e]], 1);
}

__launch_bounds__(1024)
__global__ void scan_kernel(const int* __restrict__ hist,
                            int* __restrict__ rowstart,
                            int* __restrict__ cursor)
{
    __shared__ int wsums[32];
    const int t = threadIdx.x;
    const int lane = t & 31;
    const int w = t >> 5;

    int4 v[8];
#pragma unroll
    for (int i = 0; i < 8; i++) v[i] = ((const int4*)hist)[t * 8 + i];

    int vals[32];
#pragma unroll
    for (int i = 0; i < 8; i++) {
        vals[4*i+0] = v[i].x; vals[4*i+1] = v[i].y;
        vals[4*i+2] = v[i].z; vals[4*i+3] = v[i].w;
    }
    int local[32];
    int sum = 0;
#pragma unroll
    for (int i = 0; i < 32; i++) { local[i] = sum; sum += vals[i]; }

    int inc = sum;
#pragma unroll
    for (int d = 1; d < 32; d <<= 1) {
        const int n = __shfl_up_sync(0xFFFFFFFFu, inc, d);
        if (lane >= d) inc += n;
    }
    if (lane == 31) wsums[w] = inc;
    __syncthreads();
    if (w == 0) {
        int x = wsums[lane];
#pragma unroll
        for (int d = 1; d < 32; d <<= 1) {
            const int n = __shfl_up_sync(0xFFFFFFFFu, x, d);
            if (lane >= d) x += n;
        }
        wsums[lane] = x;
    }
    __syncthreads();

    const int excl = inc - sum + (w > 0 ? wsums[w - 1] : 0);
#pragma unroll
    for (int i = 0; i < 8; i++) {
        const int4 o = make_int4(excl + local[4*i+0], excl + local[4*i+1],
                                 excl + local[4*i+2], excl + local[4*i+3]);
        ((int4*)rowstart)[t * 8 + i] = o;
        ((int4*)cursor)[t * 8 + i]   = o;
    }
    if (t == 1023) rowstart[NV] = excl + sum;
}

__launch_bounds__(256)
__global__ void place_kernel(const int* __restrict__ src,
                             const int* __restrict__ dst,
                             const int* __restrict__ et,
                             int* __restrict__ cursor,
                             int* __restrict__ sorted)
{
    const int e = blockIdx.x * 256 + threadIdx.x;
    const int d = dst[e];
    const int pos = atomicAdd(&cursor[d], 1);
    sorted[pos] = (et[e] << 15) | src[e];    // yh row index = type*NV + src
}

// ---------------------------------------------------------------------------
// Fused gather + update: one warp per dst node, MLP-8 main loop.
// out[v] = relu(y0[v] + self_b + (sum_{in} yh[row]) / max(deg,1)) [* mask]
// ---------------------------------------------------------------------------
__launch_bounds__(256)
__global__ void gather_update_kernel(const int* __restrict__ rowstart,
                                     const int* __restrict__ sorted,
                                     const float* __restrict__ y0,
                                     const __half* __restrict__ yh,
                                     const float* __restrict__ selfb,
                                     const int*  __restrict__ mask,
                                     float* __restrict__ out,
                                     int apply_mask)
{
    const int v    = blockIdx.x * 8 + (threadIdx.x >> 5);
    const int lane = threadIdx.x & 31;
    const int s = rowstart[v];
    const int e = rowstart[v + 1];

    float4 acc = make_float4(0.f, 0.f, 0.f, 0.f);
    int i = s;
    for (; i + 7 < e; i += 8) {
        int p[8];
#pragma unroll
        for (int k = 0; k < 8; k++) p[k] = sorted[i + k];
        uint2 u[8];
#pragma unroll
        for (int k = 0; k < 8; k++)
            u[k] = ((const uint2*)(yh + (size_t)p[k] * Hd))[lane];
#pragma unroll
        for (int k = 0; k < 8; k++) {
            const float2 a = __half22float2(*(const __half2*)&u[k].x);
            const float2 b = __half22float2(*(const __half2*)&u[k].y);
            acc.x += a.x; acc.y += a.y; acc.z += b.x; acc.w += b.y;
        }
    }
    if (i + 3 < e) {
        int p[4];
#pragma unroll
        for (int k = 0; k < 4; k++) p[k] = sorted[i + k];
        uint2 u[4];
#pragma unroll
        for (int k = 0; k < 4; k++)
            u[k] = ((const uint2*)(yh + (size_t)p[k] * Hd))[lane];
#pragma unroll
        for (int k = 0; k < 4; k++) {
            const float2 a = __half22float2(*(const __half2*)&u[k].x);
            const float2 b = __half22float2(*(const __half2*)&u[k].y);
            acc.x += a.x; acc.y += a.y; acc.z += b.x; acc.w += b.y;
        }
        i += 4;
    }
    for (; i < e; i++) {
        const int p = sorted[i];
        const uint2 u = ((const uint2*)(yh + (size_t)p * Hd))[lane];
        const float2 a = __half22float2(*(const __half2*)&u.x);
        const float2 b = __half22float2(*(const __half2*)&u.y);
        acc.x += a.x; acc.y += a.y; acc.z += b.x; acc.w += b.y;
    }

    const float id = 1.0f / fmaxf((float)(e - s), 1.0f);
    const float4 yv = ((const float4*)(y0 + (size_t)v * Hd))[lane];
    const float4 b  = ((const float4*)selfb)[lane];
    float m = 1.0f;
    if (apply_mask) m = (float)mask[v];

    float4 r;
    r.x = fmaxf(yv.x + b.x + acc.x * id, 0.0f) * m;
    r.y = fmaxf(yv.y + b.y + acc.y * id, 0.0f) * m;
    r.z = fmaxf(yv.z + b.z + acc.z * id, 0.0f) * m;
    r.w = fmaxf(yv.w + b.w + acc.w * id, 0.0f) * m;
    ((float4*)(out + (size_t)v * Hd))[lane] = r;
}

extern "C" void kernel_launch(void* const* d_in, const int* in_sizes, int n_in,
                              void* d_out, int out_size)
{
    const int*   cid   = (const int*)  d_in[0];
    const int*   kid   = (const int*)  d_in[1];
    const int*   mask  = (const int*)  d_in[2];
    const int*   eidx  = (const int*)  d_in[3];
    const int*   et    = (const int*)  d_in[4];
    const float* cemb  = (const float*)d_in[5];
    const float* kemb  = (const float*)d_in[6];
    const float* projW = (const float*)d_in[7];
    const float* projb = (const float*)d_in[8];
    const float* selfW = (const float*)d_in[9];
    const float* selfb = (const float*)d_in[10];
    const float* relW  = (const float*)d_in[11];

    const int* src = eidx;
    const int* dst = eidx + NE;

    float *x2, *y0, *wf, *bf, *xfb;
    __half* yh;
    int *hist, *rowstart, *cursor, *sorted;
    cudaGetSymbolAddress((void**)&x2,       g_x2);
    cudaGetSymbolAddress((void**)&y0,       g_y0);
    cudaGetSymbolAddress((void**)&yh,       g_yh);
    cudaGetSymbolAddress((void**)&wf,       g_wf);
    cudaGetSymbolAddress((void**)&bf,       g_bf);
    cudaGetSymbolAddress((void**)&xfb,      g_x_fb);
    cudaGetSymbolAddress((void**)&hist,     g_hist);
    cudaGetSymbolAddress((void**)&rowstart, g_rowstart);
    cudaGetSymbolAddress((void**)&cursor,   g_cursor);
    cudaGetSymbolAddress((void**)&sorted,   g_sorted);

    const int use_tc = g_has_tc;
    if (use_tc) {
        cudaFuncSetAttribute(tgemm9<0>, cudaFuncAttributeMaxDynamicSharedMemorySize, SMEM_TOTAL9);
        cudaFuncSetAttribute(tgemm9<1>, cudaFuncAttributeMaxDynamicSharedMemorySize, SMEM_TOTAL9);
        cudaFuncSetAttribute(wfuse_kernel, cudaFuncAttributeMaxDynamicSharedMemorySize, WF_SMEM);
    }

    // --- fork: CSR build on side stream ---
    cudaEventRecord(s_ev_fork, 0);
    cudaStreamWaitEvent(s_side, s_ev_fork, 0);
    zero_int_kernel<<<(NV + 256) / 256, 256, 0, s_side>>>(hist, NV + 1);
    hist_kernel<<<NE / 256, 256, 0, s_side>>>(dst, hist);
    scan_kernel<<<1, 1024, 0, s_side>>>(hist, rowstart, cursor);
    place_kernel<<<NE / 256, 256, 0, s_side>>>(src, dst, et, cursor, sorted);
    cudaEventRecord(s_ev_join, s_side);

    if (use_tc) {
        // Layer 0: fused weights (proj folded in), then 9-slab GEMM on embeddings
        wfuse_kernel<<<dim3(8, 9), 256, WF_SMEM>>>(projW, projb, selfW, relW, wf, bf);
        tgemm9<0><<<NV / 128, 128, SMEM_TOTAL9>>>(
            nullptr, cid, kid, cemb, kemb, wf, nullptr, nullptr, bf, y0, yh);

        cudaStreamWaitEvent(0, s_ev_join, 0);   // CSR ready before first gather
        gather_update_kernel<<<NV / 8, 256>>>(rowstart, sorted, y0, yh,
                                              selfb, mask, x2, 0);

        // Layer 1
        tgemm9<1><<<NV / 128, 128, SMEM_TOTAL9>>>(
            x2, nullptr, nullptr, nullptr, nullptr, nullptr,
            selfW + (size_t)Hd * Hd, relW + (size_t)NR * Hd * Hd,
            nullptr, y0, yh);
        gather_update_kernel<<<NV / 8, 256>>>(rowstart, sorted, y0, yh,
                                              selfb + Hd, mask, (float*)d_out, 1);
    } else {
        // Fallback: SIMT proj then per-slab SIMT GEMMs
        gemm_fb<0><<<dim3(NV / 128, 1), 256>>>(nullptr, cid, kid, cemb, kemb,
                                               nullptr, projW, projb, xfb, nullptr);
        float* cur = xfb;
        float* nxt = x2;
        for (int l = 0; l < NL; l++) {
            gemm_fb<1><<<dim3(NV / 128, NR + 1), 256>>>(
                cur, nullptr, nullptr, nullptr, nullptr,
                selfW + (size_t)l * Hd * Hd, relW + (size_t)l * NR * Hd * Hd,
                nullptr, y0, yh);
            if (l == 0) cudaStreamWaitEvent(0, s_ev_join, 0);
            float* outp = (l == NL - 1) ? (float*)d_out : nxt;
            gather_update_kernel<<<NV / 8, 256>>>(rowstart, sorted, y0, yh,
                                                  selfb + (size_t)l * Hd, mask, outp,
                                                  (l == NL - 1) ? 1 : 0);
            float* tmp = cur; cur = nxt; nxt = tmp;
        }
    }
}

// round 16
// speedup vs baseline: 1.0939x; 1.0939x over previous
#include <cuda_runtime.h>
#include <cuda_bf16.h>
#include <cuda_fp16.h>
#include <cstdint>

// ---------------------------------------------------------------------------
// Arch feature gate: tcgen05 exists only on sm_103a / family 103f.
// ---------------------------------------------------------------------------
#if defined(__CUDA_ARCH__) && (defined(__CUDA_ARCH_FEAT_SM103_ALL) || \
    (defined(__CUDA_ARCH_FAMILY_SPECIFIC__) && (__CUDA_ARCH_FAMILY_SPECIFIC__ == 1030)))
#define TC_OK 1
#else
#define TC_OK 0
#endif

// Problem constants (fixed by dataset)
constexpr int NV = 32768;          // B*N nodes
constexpr int Hd = 128;            // hidden
constexpr int NE = 524288;         // edges
constexpr int NR = 8;              // relations
constexpr int NL = 2;              // layers
constexpr int NSLAB = NR + 1;      // 9: slab 0 = self (fp32), 1..8 = relations (fp16)

// Scratch (static device globals; no allocation at runtime)
__device__ float  g_x2[(size_t)NV * Hd];
__device__ float  g_y0[(size_t)NV * Hd];              // self-term slab, fp32
__device__ __half g_yh[(size_t)NR * NV * Hd];         // relation message slabs, fp16
__device__ float  g_wf[(size_t)NSLAB * Hd * Hd];      // fused layer-0 weights W_j @ projW
__device__ float  g_bf[NSLAB * Hd];                   // fused layer-0 biases  W_j @ projb
__device__ __align__(16) int g_hist    [NV + 4];
__device__ __align__(16) int g_rowstart[NV + 4];
__device__ __align__(16) int g_cursor  [NV + 4];
__device__ int    g_sorted [NE];                      // (type<<15) | src, grouped by dst
__device__ int    g_tc_flag;

// ---------------------------------------------------------------------------
// Static-init setup: capability probe + side stream/events (pre-capture)
// ---------------------------------------------------------------------------
__global__ void probe_kernel() { g_tc_flag = TC_OK; }

static cudaStream_t s_side;
static cudaEvent_t  s_ev_fork, s_ev_join;

static int setup_once() {
    int v = 0;
    probe_kernel<<<1, 1>>>();
    cudaMemcpyFromSymbol(&v, g_tc_flag, sizeof(int));
    cudaStreamCreateWithFlags(&s_side, cudaStreamNonBlocking);
    cudaEventCreateWithFlags(&s_ev_fork, cudaEventDisableTiming);
    cudaEventCreateWithFlags(&s_ev_join, cudaEventDisableTiming);
    return v;
}
static const int g_has_tc = setup_once();

// ---------------------------------------------------------------------------
// PTX helpers
// ---------------------------------------------------------------------------
__device__ __forceinline__ uint32_t smem_u32(const void* p) {
    uint32_t a;
    asm("{ .reg .u64 t; cvta.to.shared.u64 t, %1; cvt.u32.u64 %0, t; }" : "=r"(a) : "l"(p));
    return a;
}
__device__ __forceinline__ uint32_t elect_one() {
    uint32_t p;
    asm volatile("{\n\t.reg .pred p;\n\telect.sync _|p, 0xFFFFFFFF;\n\tselp.b32 %0, 1, 0, p;\n\t}" : "=r"(p));
    return p;
}
__device__ __forceinline__ uint32_t f2tf32(float f) {
    uint32_t u;
    asm("cvt.rna.tf32.f32 %0, %1;" : "=r"(u) : "f"(f));
    return u;
}

#if TC_OK
#define TC_ALLOC(sm, n)   asm volatile("tcgen05.alloc.cta_group::1.sync.aligned.shared::cta.b32 [%0], %1;" :: "r"(sm), "r"(n) : "memory")
#define TC_DEALLOC(t, n)  asm volatile("tcgen05.dealloc.cta_group::1.sync.aligned.b32 %0, %1;" :: "r"(t), "r"(n))
#define TC_RELINQ()       asm volatile("tcgen05.relinquish_alloc_permit.cta_group::1.sync.aligned;")
#define TC_COMMIT(mb)     asm volatile("tcgen05.commit.cta_group::1.mbarrier::arrive::one.shared::cluster.b64 [%0];" :: "r"(mb) : "memory")
#define TC_WAIT_LD()      asm volatile("tcgen05.wait::ld.sync.aligned;" ::: "memory")
#define TC_FENCE_AFTER()  asm volatile("tcgen05.fence::after_thread_sync;" ::: "memory")
#define TC_FENCE_BEFORE() asm volatile("tcgen05.fence::before_thread_sync;" ::: "memory")
#endif

#define MBAR_INIT(mb, c)  asm volatile("mbarrier.init.shared.b64 [%0], %1;" :: "r"(mb), "r"(c) : "memory")
#define MBAR_INVAL(mb)    asm volatile("mbarrier.inval.shared.b64 [%0];" :: "r"(mb) : "memory")

__device__ __forceinline__ void mbar_wait(uint32_t mb, uint32_t parity) {
    asm volatile(
        "{\n\t.reg .pred P1;\n\t"
        "WL_%=:\n\t"
        "mbarrier.try_wait.parity.acquire.cta.shared::cta.b64 P1, [%0], %1, 0x989680;\n\t"
        "@P1 bra.uni WD_%=;\n\t"
        "bra.uni WL_%=;\n\t"
        "WD_%=:\n\t}"
        :: "r"(mb), "r"(parity) : "memory");
}

#if TC_OK
__device__ __forceinline__ void mma_tf32_ss(uint32_t d, uint64_t ad, uint64_t bd,
                                            uint32_t idesc, uint32_t en) {
    asm volatile(
        "{\n\t.reg .pred p;\n\tsetp.ne.u32 p, %5, 0;\n\t"
        "tcgen05.mma.cta_group::1.kind::tf32 [%0], %1, %2, %3, {%4, %4, %4, %4}, p;\n\t}"
        :: "r"(d), "l"(ad), "l"(bd), "r"(idesc), "r"(0u), "r"(en) : "memory");
}

__device__ __forceinline__ void ldtm_x32(uint32_t* r, uint32_t addr) {
    asm volatile(
        "tcgen05.ld.sync.aligned.32x32b.x32.b32 "
        "{%0,%1,%2,%3,%4,%5,%6,%7,%8,%9,%10,%11,%12,%13,%14,%15,"
        "%16,%17,%18,%19,%20,%21,%22,%23,%24,%25,%26,%27,%28,%29,%30,%31}, [%32];"
        : "=r"(r[0]), "=r"(r[1]), "=r"(r[2]), "=r"(r[3]), "=r"(r[4]), "=r"(r[5]), "=r"(r[6]), "=r"(r[7]),
          "=r"(r[8]), "=r"(r[9]), "=r"(r[10]), "=r"(r[11]), "=r"(r[12]), "=r"(r[13]), "=r"(r[14]), "=r"(r[15]),
          "=r"(r[16]), "=r"(r[17]), "=r"(r[18]), "=r"(r[19]), "=r"(r[20]), "=r"(r[21]), "=r"(r[22]), "=r"(r[23]),
          "=r"(r[24]), "=r"(r[25]), "=r"(r[26]), "=r"(r[27]), "=r"(r[28]), "=r"(r[29]), "=r"(r[30]), "=r"(r[31])
        : "r"(addr));
}
#endif

// SW128 K-major blocked-atom layout for a 128x128 fp32 tile.
__device__ __forceinline__ uint32_t tile_off(int row, int k) {
    uint32_t off = ((uint32_t)((k >> 5) * 16 + (row >> 3)) << 10)
                 + ((uint32_t)(row & 7) << 7) + ((uint32_t)(k & 31) << 2);
    return off ^ ((off >> 3) & 0x70);
}

// smem descriptor: SW128, version=1, LBO=1, SBO=64
__device__ __forceinline__ uint64_t make_desc(uint32_t base) {
    const uint64_t BASE = (uint64_t(2) << 61) | (uint64_t(1) << 46)
                        | (uint64_t(64) << 32) | (uint64_t(1) << 16);
    return BASE | ((uint64_t)(base >> 4) & 0x3FFF);
}

constexpr uint32_t IDESC_TF32 = (1u << 4) | (2u << 7) | (2u << 10) | (16u << 17) | (8u << 24);

// Dynamic SMEM layout (tgemm9)
constexpr int SMEM_TMEM = 0;
constexpr int SMEM_MB0  = 8;
constexpr int SMEM_MB1  = 16;
constexpr int SMEM_A    = 1024;
constexpr int SMEM_W0   = SMEM_A  + 65536;
constexpr int SMEM_W1   = SMEM_W0 + 65536;
constexpr int SMEM_TOTAL9 = SMEM_W1 + 65536 + 128;
constexpr int WF_SMEM = (Hd * Hd + 16 * Hd) * 4;   // projW (64K) + 16 W rows (8K)

// ---------------------------------------------------------------------------
// Weight fusion for layer 0:  wf[j] = W_j @ projW,  bf[j] = W_j @ projb
// ---------------------------------------------------------------------------
__global__ void __launch_bounds__(256)
wfuse_kernel(const float* __restrict__ projW, const float* __restrict__ projb,
             const float* __restrict__ selfW, const float* __restrict__ relW,
             float* __restrict__ wf, float* __restrict__ bf)
{
    extern __shared__ float sdyn[];
    float* sP = sdyn;                 // [128][128] projW
    float* sW = sdyn + Hd * Hd;       // [16][128]  W_j rows

    const int j  = blockIdx.y;
    const int rb = blockIdx.x;        // row block (16 rows)
    const int t  = threadIdx.x;
    const float* Wj = (j == 0) ? selfW : (relW + (size_t)(j - 1) * Hd * Hd);

    for (int i = t; i < Hd * Hd / 4; i += 256)
        ((float4*)sP)[i] = ((const float4*)projW)[i];
    for (int i = t; i < 16 * Hd / 4; i += 256)
        ((float4*)sW)[i] = ((const float4*)(Wj + (size_t)rb * 16 * Hd))[i];
    __syncthreads();

    const int rl   = t >> 4;          // local row 0..15
    const int hseg = t & 15;          // 8-col segment
    float acc[8] = {0, 0, 0, 0, 0, 0, 0, 0};
    float bacc = 0.0f;
#pragma unroll 4
    for (int k = 0; k < Hd; k++) {
        const float wv = sW[rl * Hd + k];
        const float* pr = sP + k * Hd + hseg * 8;
#pragma unroll
        for (int hh = 0; hh < 8; hh++) acc[hh] += wv * pr[hh];
        if (hseg == 0) bacc += wv * projb[k];
    }
    const int g = rb * 16 + rl;
    float* orow = wf + ((size_t)j * Hd + g) * Hd + hseg * 8;
#pragma unroll
    for (int hh = 0; hh < 8; hh++) orow[hh] = acc[hh];
    if (hseg == 0) bf[j * Hd + g] = bacc;
}

// ---------------------------------------------------------------------------
// 9-slab GEMM: one CTA = one 128-row x-block; A loaded once; 9 weights stream
// through double-buffered smem; D ping-pongs between two TMEM buffers.
// MODE 0 (layer 0): A = cemb[cid]+kemb[kid] gathered; weights = fused wf + bf.
// MODE 1 (layer 1): A = node states; weights = selfW / relW; no bias.
// Slab 0 -> y0 (fp32); slabs 1..8 -> yh (fp16).
// ---------------------------------------------------------------------------
template <int MODE>
__global__ void __launch_bounds__(128, 1)
tgemm9(const float* __restrict__ Asrc,
       const int* __restrict__ cid, const int* __restrict__ kid,
       const float* __restrict__ cemb, const float* __restrict__ kemb,
       const float* __restrict__ wf,
       const float* __restrict__ selfW, const float* __restrict__ relW,
       const float* __restrict__ biasf,
       float* __restrict__ Y0out, __half* __restrict__ Yhout)
{
#if TC_OK
    extern __shared__ char smem[];
    const uint32_t sb = smem_u32(smem);
    const int tid = threadIdx.x;
    const int wid = tid >> 5;
    const int lid = tid & 31;
    const int vbase = blockIdx.x * 128;

    if (wid == 0) TC_ALLOC(sb + SMEM_TMEM, 256);
    else          TC_RELINQ();
    __syncthreads();
    uint32_t tmem;
    asm volatile("ld.shared.b32 %0, [%1];" : "=r"(tmem) : "r"(sb + SMEM_TMEM));

    if (tid == 0) {
        MBAR_INIT(sb + SMEM_MB0, 1);
        MBAR_INIT(sb + SMEM_MB1, 1);
    }

    // A row (row = tid)
    if (MODE == 0) {
        const float4* ar = (const float4*)(cemb + (size_t)cid[vbase + tid] * Hd);
        const float4* kr = (const float4*)(kemb + (size_t)kid[vbase + tid] * Hd);
#pragma unroll
        for (int c4 = 0; c4 < 32; c4++) {
            float4 a = ar[c4];
            const float4 k = kr[c4];
            a.x += k.x; a.y += k.y; a.z += k.z; a.w += k.w;
            *(uint4*)(smem + SMEM_A + tile_off(tid, c4 * 4)) =
                make_uint4(f2tf32(a.x), f2tf32(a.y), f2tf32(a.z), f2tf32(a.w));
        }
    } else {
        const float4* ar = (const float4*)(Asrc + (size_t)(vbase + tid) * Hd);
#pragma unroll
        for (int c4 = 0; c4 < 32; c4++) {
            const float4 a = ar[c4];
            *(uint4*)(smem + SMEM_A + tile_off(tid, c4 * 4)) =
                make_uint4(f2tf32(a.x), f2tf32(a.y), f2tf32(a.z), f2tf32(a.w));
        }
    }
    // W_0 into buffer 0
    {
        const float* W0 = (MODE == 0) ? wf : selfW;
        const float4* wr = (const float4*)(W0 + (size_t)tid * Hd);
#pragma unroll
        for (int c4 = 0; c4 < 32; c4++) {
            const float4 w = wr[c4];
            *(uint4*)(smem + SMEM_W0 + tile_off(tid, c4 * 4)) =
                make_uint4(f2tf32(w.x), f2tf32(w.y), f2tf32(w.z), f2tf32(w.w));
        }
    }
    asm volatile("fence.proxy.async.shared::cta;" ::: "memory");
    TC_FENCE_BEFORE();
    __syncthreads();

    const uint64_t ad = make_desc(sb + SMEM_A);
    const int row = wid * 32 + lid;

    for (int j = 0; j < NSLAB; j++) {
        const int buf = j & 1;
        const uint32_t dtm = tmem + buf * 128;

        if (wid == 0) {
            TC_FENCE_AFTER();
            const uint64_t bd = make_desc(sb + (buf ? SMEM_W1 : SMEM_W0));
            if (elect_one()) {
#pragma unroll
                for (int s = 0; s < 16; s++) {
                    const uint64_t off = (uint64_t)((s >> 2) * 1024 + (s & 3) * 2);
                    mma_tf32_ss(dtm, ad + off, bd + off, IDESC_TF32, s > 0 ? 1u : 0u);
                }
                TC_COMMIT(sb + (buf ? SMEM_MB1 : SMEM_MB0));
            }
        }

        if (j + 1 < NSLAB) {
            const float* Wn = (MODE == 0) ? (wf + (size_t)(j + 1) * Hd * Hd)
                                          : (relW + (size_t)j * Hd * Hd);
            const float4* wr = (const float4*)(Wn + (size_t)tid * Hd);
            char* wb = smem + ((j + 1) & 1 ? SMEM_W1 : SMEM_W0);
#pragma unroll
            for (int c4 = 0; c4 < 32; c4++) {
                const float4 w = wr[c4];
                *(uint4*)(wb + tile_off(tid, c4 * 4)) =
                    make_uint4(f2tf32(w.x), f2tf32(w.y), f2tf32(w.z), f2tf32(w.w));
            }
        }

        mbar_wait(sb + (buf ? SMEM_MB1 : SMEM_MB0), (j >> 1) & 1);
        TC_FENCE_AFTER();

        const float* bp = (MODE == 0) ? (biasf + j * Hd) : nullptr;
        if (j == 0) {
            float* crow = Y0out + (size_t)(vbase + row) * Hd;
#pragma unroll
            for (int ch = 0; ch < 4; ch++) {
                uint32_t d[32];
                ldtm_x32(d, dtm + ch * 32);
                TC_WAIT_LD();
#pragma unroll
                for (int q = 0; q < 8; q++) {
                    float4 o = make_float4(
                        __uint_as_float(d[q*4+0]), __uint_as_float(d[q*4+1]),
                        __uint_as_float(d[q*4+2]), __uint_as_float(d[q*4+3]));
                    if (MODE == 0) {
                        o.x += bp[ch*32 + q*4+0]; o.y += bp[ch*32 + q*4+1];
                        o.z += bp[ch*32 + q*4+2]; o.w += bp[ch*32 + q*4+3];
                    }
                    *(float4*)(crow + ch * 32 + q * 4) = o;
                }
            }
        } else {
            __half* crow = Yhout + ((size_t)(j - 1) * NV + (size_t)(vbase + row)) * Hd;
#pragma unroll
            for (int ch = 0; ch < 4; ch++) {
                uint32_t d[32];
                ldtm_x32(d, dtm + ch * 32);
                TC_WAIT_LD();
                uint32_t h2[16];
#pragma unroll
                for (int k2 = 0; k2 < 16; k2++) {
                    float lo = __uint_as_float(d[2*k2]);
                    float hi = __uint_as_float(d[2*k2+1]);
                    if (MODE == 0) { lo += bp[ch*32 + 2*k2]; hi += bp[ch*32 + 2*k2+1]; }
                    const __half2 hh = __floats2half2_rn(lo, hi);
                    h2[k2] = *(const uint32_t*)&hh;
                }
                uint4* dstp = (uint4*)(crow + ch * 32);
#pragma unroll
                for (int q = 0; q < 4; q++)
                    dstp[q] = make_uint4(h2[4*q+0], h2[4*q+1], h2[4*q+2], h2[4*q+3]);
            }
        }
        TC_FENCE_BEFORE();
        asm volatile("fence.proxy.async.shared::cta;" ::: "memory");
        __syncthreads();
    }

    if (tid == 0) { MBAR_INVAL(sb + SMEM_MB0); MBAR_INVAL(sb + SMEM_MB1); }
    __syncthreads();
    if (wid == 0) TC_DEALLOC(tmem, 256);
#endif
}

// ---------------------------------------------------------------------------
// Fallback SIMT fp32 GEMM — used only if tcgen05 unavailable.
// ---------------------------------------------------------------------------
__device__ float g_x_fb[(size_t)NV * Hd];   // fallback-only x buffer

template <int MODE>
__launch_bounds__(256)
__global__ void gemm_fb(const float* __restrict__ Asrc,
                        const int*   __restrict__ cid,
                        const int*   __restrict__ kid,
                        const float* __restrict__ cemb,
                        const float* __restrict__ kemb,
                        const float* __restrict__ selfW,
                        const float* __restrict__ relW,
                        const float* __restrict__ bias,
                        float* __restrict__ Cout,
                        __half* __restrict__ Hout)
{
    __shared__ float As[32][132];
    __shared__ float Ws[32][132];
    __shared__ int   s_cid[128];
    __shared__ int   s_kid[128];

    const int tid = threadIdx.x;
    const int tx = tid & 15;
    const int ty = tid >> 4;
    const int vbase = blockIdx.x * 128;

    const float* W;
    float* C = nullptr;
    __half* CH = nullptr;
    int jslab = 0;
    if (MODE == 0) {
        W = relW;
        C = Cout + (size_t)vbase * Hd;
    } else {
        jslab = blockIdx.y;
        W = (jslab == 0) ? selfW : (relW + (size_t)(jslab - 1) * Hd * Hd);
        if (jslab == 0) C = Cout + (size_t)vbase * Hd;
        else            CH = Hout + ((size_t)(jslab - 1) * NV + (size_t)vbase) * Hd;
    }

    if (MODE == 0) {
        if (tid < 128) {
            s_cid[tid] = cid[vbase + tid];
            s_kid[tid] = kid[vbase + tid];
        }
        __syncthreads();
    }

    float acc[8][8];
#pragma unroll
    for (int i = 0; i < 8; i++)
#pragma unroll
        for (int j = 0; j < 8; j++) acc[i][j] = 0.0f;

#pragma unroll
    for (int kc = 0; kc < Hd; kc += 32) {
#pragma unroll
        for (int rep = 0; rep < 4; rep++) {
            const int i   = tid + rep * 256;
            const int r   = i >> 3;
            const int c4  = i & 7;
            float4 a;
            if (MODE == 0) {
                const float4 av = ((const float4*)(cemb + (size_t)s_cid[r] * Hd + kc))[c4];
                const float4 kv = ((const float4*)(kemb + (size_t)s_kid[r] * Hd + kc))[c4];
                a = make_float4(av.x + kv.x, av.y + kv.y, av.z + kv.z, av.w + kv.w);
            } else {
                a = *(const float4*)(Asrc + (size_t)(vbase + r) * Hd + kc + c4 * 4);
            }
            As[c4 * 4 + 0][r] = a.x; As[c4 * 4 + 1][r] = a.y;
            As[c4 * 4 + 2][r] = a.z; As[c4 * 4 + 3][r] = a.w;
            const float4 w = *(const float4*)(W + (size_t)r * Hd + kc + c4 * 4);
            Ws[c4 * 4 + 0][r] = w.x; Ws[c4 * 4 + 1][r] = w.y;
            Ws[c4 * 4 + 2][r] = w.z; Ws[c4 * 4 + 3][r] = w.w;
        }
        __syncthreads();

#pragma unroll
        for (int k = 0; k < 32; k++) {
            const float4 a0 = *(const float4*)&As[k][ty * 8];
            const float4 a1 = *(const float4*)&As[k][ty * 8 + 4];
            const float4 w0 = *(const float4*)&Ws[k][tx * 8];
            const float4 w1 = *(const float4*)&Ws[k][tx * 8 + 4];
            const float a[8] = {a0.x, a0.y, a0.z, a0.w, a1.x, a1.y, a1.z, a1.w};
            const float w[8] = {w0.x, w0.y, w0.z, w0.w, w1.x, w1.y, w1.z, w1.w};
#pragma unroll
            for (int i = 0; i < 8; i++)
#pragma unroll
                for (int j = 0; j < 8; j++) acc[i][j] += a[i] * w[j];
        }
        __syncthreads();
    }

    float b0[8];
    if (MODE == 0) {
#pragma unroll
        for (int j = 0; j < 8; j++) b0[j] = bias[tx * 8 + j];
    }
#pragma unroll
    for (int i = 0; i < 8; i++) {
        const int r = ty * 8 + i;
        if (MODE == 0) {
            *(float4*)(C + (size_t)r * Hd + tx * 8) =
                make_float4(acc[i][0] + b0[0], acc[i][1] + b0[1],
                            acc[i][2] + b0[2], acc[i][3] + b0[3]);
            *(float4*)(C + (size_t)r * Hd + tx * 8 + 4) =
                make_float4(acc[i][4] + b0[4], acc[i][5] + b0[5],
                            acc[i][6] + b0[6], acc[i][7] + b0[7]);
        } else if (jslab == 0) {
            *(float4*)(C + (size_t)r * Hd + tx * 8) =
                make_float4(acc[i][0], acc[i][1], acc[i][2], acc[i][3]);
            *(float4*)(C + (size_t)r * Hd + tx * 8 + 4) =
                make_float4(acc[i][4], acc[i][5], acc[i][6], acc[i][7]);
        } else {
            uint32_t h2[4];
#pragma unroll
            for (int q = 0; q < 4; q++) {
                const __half2 hh = __floats2half2_rn(acc[i][2*q], acc[i][2*q+1]);
                h2[q] = *(const uint32_t*)&hh;
            }
            *(uint4*)(CH + (size_t)r * Hd + tx * 8) = make_uint4(h2[0], h2[1], h2[2], h2[3]);
        }
    }
}

// ---------------------------------------------------------------------------
// CSR build: histogram -> fast scan (1 CTA, vectorized + shfl) -> placement
// hist/place process 4 edges per thread via int4 loads.
// ---------------------------------------------------------------------------
__launch_bounds__(256)
__global__ void zero_int_kernel(int* __restrict__ p, int n)
{
    const int i = blockIdx.x * 256 + threadIdx.x;
    if (i < n) p[i] = 0;
}

__launch_bounds__(256)
__global__ void hist_kernel(const int* __restrict__ dst, int* __restrict__ hist)
{
    const int e4 = blockIdx.x * 256 + threadIdx.x;
    const int4 d = ((const int4*)dst)[e4];
    atomicAdd(&hist[d.x], 1);
    atomicAdd(&hist[d.y], 1);
    atomicAdd(&hist[d.z], 1);
    atomicAdd(&hist[d.w], 1);
}

__launch_bounds__(1024)
__global__ void scan_kernel(const int* __restrict__ hist,
                            int* __restrict__ rowstart,
                            int* __restrict__ cursor)
{
    __shared__ int wsums[32];
    const int t = threadIdx.x;
    const int lane = t & 31;
    const int w = t >> 5;

    int4 v[8];
#pragma unroll
    for (int i = 0; i < 8; i++) v[i] = ((const int4*)hist)[t * 8 + i];

    int vals[32];
#pragma unroll
    for (int i = 0; i < 8; i++) {
        vals[4*i+0] = v[i].x; vals[4*i+1] = v[i].y;
        vals[4*i+2] = v[i].z; vals[4*i+3] = v[i].w;
    }
    int local[32];
    int sum = 0;
#pragma unroll
    for (int i = 0; i < 32; i++) { local[i] = sum; sum += vals[i]; }

    int inc = sum;
#pragma unroll
    for (int d = 1; d < 32; d <<= 1) {
        const int n = __shfl_up_sync(0xFFFFFFFFu, inc, d);
        if (lane >= d) inc += n;
    }
    if (lane == 31) wsums[w] = inc;
    __syncthreads();
    if (w == 0) {
        int x = wsums[lane];
#pragma unroll
        for (int d = 1; d < 32; d <<= 1) {
            const int n = __shfl_up_sync(0xFFFFFFFFu, x, d);
            if (lane >= d) x += n;
        }
        wsums[lane] = x;
    }
    __syncthreads();

    const int excl = inc - sum + (w > 0 ? wsums[w - 1] : 0);
#pragma unroll
    for (int i = 0; i < 8; i++) {
        const int4 o = make_int4(excl + local[4*i+0], excl + local[4*i+1],
                                 excl + local[4*i+2], excl + local[4*i+3]);
        ((int4*)rowstart)[t * 8 + i] = o;
        ((int4*)cursor)[t * 8 + i]   = o;
    }
    if (t == 1023) rowstart[NV] = excl + sum;
}

__launch_bounds__(256)
__global__ void place_kernel(const int* __restrict__ src,
                             const int* __restrict__ dst,
                             const int* __restrict__ et,
                             int* __restrict__ cursor,
                             int* __restrict__ sorted)
{
    const int e4 = blockIdx.x * 256 + threadIdx.x;
    const int4 s = ((const int4*)src)[e4];
    const int4 d = ((const int4*)dst)[e4];
    const int4 t = ((const int4*)et)[e4];
    int p;
    p = atomicAdd(&cursor[d.x], 1); sorted[p] = (t.x << 15) | s.x;
    p = atomicAdd(&cursor[d.y], 1); sorted[p] = (t.y << 15) | s.y;
    p = atomicAdd(&cursor[d.z], 1); sorted[p] = (t.z << 15) | s.z;
    p = atomicAdd(&cursor[d.w], 1); sorted[p] = (t.w << 15) | s.w;
}

// ---------------------------------------------------------------------------
// Fused gather + update: one warp per dst node (R12-proven MLP-4 loop).
// out[v] = relu(y0[v] + self_b + (sum_{in} yh[row]) / max(deg,1)) [* mask]
// ---------------------------------------------------------------------------
__launch_bounds__(256)
__global__ void gather_update_kernel(const int* __restrict__ rowstart,
                                     const int* __restrict__ sorted,
                                     const float* __restrict__ y0,
                                     const __half* __restrict__ yh,
                                     const float* __restrict__ selfb,
                                     const int*  __restrict__ mask,
                                     float* __restrict__ out,
                                     int apply_mask)
{
    const int v    = blockIdx.x * 8 + (threadIdx.x >> 5);
    const int lane = threadIdx.x & 31;
    const int s = rowstart[v];
    const int e = rowstart[v + 1];

    float4 acc = make_float4(0.f, 0.f, 0.f, 0.f);
    int i = s;
    for (; i + 3 < e; i += 4) {
        const int p0 = sorted[i], p1 = sorted[i + 1], p2 = sorted[i + 2], p3 = sorted[i + 3];
        const uint2 u0 = ((const uint2*)(yh + (size_t)p0 * Hd))[lane];
        const uint2 u1 = ((const uint2*)(yh + (size_t)p1 * Hd))[lane];
        const uint2 u2 = ((const uint2*)(yh + (size_t)p2 * Hd))[lane];
        const uint2 u3 = ((const uint2*)(yh + (size_t)p3 * Hd))[lane];
        const float2 a0 = __half22float2(*(const __half2*)&u0.x);
        const float2 b0 = __half22float2(*(const __half2*)&u0.y);
        const float2 a1 = __half22float2(*(const __half2*)&u1.x);
        const float2 b1 = __half22float2(*(const __half2*)&u1.y);
        const float2 a2 = __half22float2(*(const __half2*)&u2.x);
        const float2 b2 = __half22float2(*(const __half2*)&u2.y);
        const float2 a3 = __half22float2(*(const __half2*)&u3.x);
        const float2 b3 = __half22float2(*(const __half2*)&u3.y);
        acc.x += (a0.x + a1.x) + (a2.x + a3.x);
        acc.y += (a0.y + a1.y) + (a2.y + a3.y);
        acc.z += (b0.x + b1.x) + (b2.x + b3.x);
        acc.w += (b0.y + b1.y) + (b2.y + b3.y);
    }
    for (; i < e; i++) {
        const int p = sorted[i];
        const uint2 u = ((const uint2*)(yh + (size_t)p * Hd))[lane];
        const float2 a = __half22float2(*(const __half2*)&u.x);
        const float2 b = __half22float2(*(const __half2*)&u.y);
        acc.x += a.x; acc.y += a.y; acc.z += b.x; acc.w += b.y;
    }

    const float id = 1.0f / fmaxf((float)(e - s), 1.0f);
    const float4 yv = ((const float4*)(y0 + (size_t)v * Hd))[lane];
    const float4 b  = ((const float4*)selfb)[lane];
    float m = 1.0f;
    if (apply_mask) m = (float)mask[v];

    float4 r;
    r.x = fmaxf(yv.x + b.x + acc.x * id, 0.0f) * m;
    r.y = fmaxf(yv.y + b.y + acc.y * id, 0.0f) * m;
    r.z = fmaxf(yv.z + b.z + acc.z * id, 0.0f) * m;
    r.w = fmaxf(yv.w + b.w + acc.w * id, 0.0f) * m;
    ((float4*)(out + (size_t)v * Hd))[lane] = r;
}

extern "C" void kernel_launch(void* const* d_in, const int* in_sizes, int n_in,
                              void* d_out, int out_size)
{
    const int*   cid   = (const int*)  d_in[0];
    const int*   kid   = (const int*)  d_in[1];
    const int*   mask  = (const int*)  d_in[2];
    const int*   eidx  = (const int*)  d_in[3];
    const int*   et    = (const int*)  d_in[4];
    const float* cemb  = (const float*)d_in[5];
    const float* kemb  = (const float*)d_in[6];
    const float* projW = (const float*)d_in[7];
    const float* projb = (const float*)d_in[8];
    const float* selfW = (const float*)d_in[9];
    const float* selfb = (const float*)d_in[10];
    const float* relW  = (const float*)d_in[11];

    const int* src = eidx;
    const int* dst = eidx + NE;

    float *x2, *y0, *wf, *bf, *xfb;
    __half* yh;
    int *hist, *rowstart, *cursor, *sorted;
    cudaGetSymbolAddress((void**)&x2,       g_x2);
    cudaGetSymbolAddress((void**)&y0,       g_y0);
    cudaGetSymbolAddress((void**)&yh,       g_yh);
    cudaGetSymbolAddress((void**)&wf,       g_wf);
    cudaGetSymbolAddress((void**)&bf,       g_bf);
    cudaGetSymbolAddress((void**)&xfb,      g_x_fb);
    cudaGetSymbolAddress((void**)&hist,     g_hist);
    cudaGetSymbolAddress((void**)&rowstart, g_rowstart);
    cudaGetSymbolAddress((void**)&cursor,   g_cursor);
    cudaGetSymbolAddress((void**)&sorted,   g_sorted);

    const int use_tc = g_has_tc;
    if (use_tc) {
        cudaFuncSetAttribute(tgemm9<0>, cudaFuncAttributeMaxDynamicSharedMemorySize, SMEM_TOTAL9);
        cudaFuncSetAttribute(tgemm9<1>, cudaFuncAttributeMaxDynamicSharedMemorySize, SMEM_TOTAL9);
        cudaFuncSetAttribute(wfuse_kernel, cudaFuncAttributeMaxDynamicSharedMemorySize, WF_SMEM);
    }

    // --- fork: CSR build on side stream ---
    cudaEventRecord(s_ev_fork, 0);
    cudaStreamWaitEvent(s_side, s_ev_fork, 0);
    zero_int_kernel<<<(NV + 256) / 256, 256, 0, s_side>>>(hist, NV + 1);
    hist_kernel<<<NE / 1024, 256, 0, s_side>>>(dst, hist);
    scan_kernel<<<1, 1024, 0, s_side>>>(hist, rowstart, cursor);
    place_kernel<<<NE / 1024, 256, 0, s_side>>>(src, dst, et, cursor, sorted);
    cudaEventRecord(s_ev_join, s_side);

    if (use_tc) {
        // Layer 0: fused weights (proj folded in), then 9-slab GEMM on embeddings
        wfuse_kernel<<<dim3(8, 9), 256, WF_SMEM>>>(projW, projb, selfW, relW, wf, bf);
        tgemm9<0><<<NV / 128, 128, SMEM_TOTAL9>>>(
            nullptr, cid, kid, cemb, kemb, wf, nullptr, nullptr, bf, y0, yh);

        cudaStreamWaitEvent(0, s_ev_join, 0);   // CSR ready before first gather
        gather_update_kernel<<<NV / 8, 256>>>(rowstart, sorted, y0, yh,
                                              selfb, mask, x2, 0);

        // Layer 1
        tgemm9<1><<<NV / 128, 128, SMEM_TOTAL9>>>(
            x2, nullptr, nullptr, nullptr, nullptr, nullptr,
            selfW + (size_t)Hd * Hd, relW + (size_t)NR * Hd * Hd,
            nullptr, y0, yh);
        gather_update_kernel<<<NV / 8, 256>>>(rowstart, sorted, y0, yh,
                                              selfb + Hd, mask, (float*)d_out, 1);
    } else {
        // Fallback: SIMT proj then per-slab SIMT GEMMs
        gemm_fb<0><<<dim3(NV / 128, 1), 256>>>(nullptr, cid, kid, cemb, kemb,
                                               nullptr, projW, projb, xfb, nullptr);
        float* cur = xfb;
        float* nxt = x2;
        for (int l = 0; l < NL; l++) {
            gemm_fb<1><<<dim3(NV / 128, NR + 1), 256>>>(
                cur, nullptr, nullptr, nullptr, nullptr,
                selfW + (size_t)l * Hd * Hd, relW + (size_t)l * NR * Hd * Hd,
                nullptr, y0, yh);
            if (l == 0) cudaStreamWaitEvent(0, s_ev_join, 0);
            float* outp = (l == NL - 1) ? (float*)d_out : nxt;
            gather_update_kernel<<<NV / 8, 256>>>(rowstart, sorted, y0, yh,
                                                  selfb + (size_t)l * Hd, mask, outp,
                                                  (l == NL - 1) ? 1 : 0);
            float* tmp = cur; cur = nxt; nxt = tmp;
        }
    }
}